// round 7
// baseline (speedup 1.0000x reference)
#include <cuda_runtime.h>
#include <cstdint>
#include <cstddef>

// Problem constants (fixed shapes)
#define SEQ_L   8192
#define DMODEL  1024
#define NBATCH  2
#define NGROUP  256
#define LCACHE  128

// Tiling
#define T_TILE  128
#define TPC     4                        // t-tiles per CTA (halo reuse across tiles)
#define NPAIR   16                       // 16 channel pairs = 32 channels per CTA
#define ZSTR    257                      // padded row stride (float2) -> conflict-free LDS
#define KSTRF   132                      // filter row stride in floats (16B-aligned rows)
#define NTHREADS 128

#define SMEM_BYTES (NPAIR * ZSTR * (int)sizeof(float2) + 8 * KSTRF * (int)sizeof(float))

// Decayed filter, precomputed once per launch: k[g,tau] = h[g,tau]*exp(-10^(2g/255) * tau/127)
__device__ float g_k[NGROUP * LCACHE];

__global__ void build_filter(const float* __restrict__ h) {
    int g = blockIdx.x;
    int tau = threadIdx.x;
    float decay = exp10f(2.0f * (float)g * (1.0f / 255.0f));
    float t = (float)tau * (1.0f / 127.0f);
    g_k[g * LCACHE + tau] = h[g * LCACHE + tau] * expf(-decay * t);
}

// 64-bit packed fp32 helpers (f32x2: 2 FMA lanes per issue)
__device__ __forceinline__ unsigned long long ld2(const float2* p) {
    return *reinterpret_cast<const unsigned long long*>(p);
}
__device__ __forceinline__ void fma2(unsigned long long& d, unsigned long long a, unsigned long long b) {
    asm("fma.rn.f32x2 %0, %1, %2, %0;" : "+l"(d) : "l"(a), "l"(b));
}
__device__ __forceinline__ unsigned long long pack2(float v) {
    unsigned long long d;
    asm("mov.b64 %0, {%1, %1};" : "=l"(d) : "f"(v));
    return d;
}

__global__ __launch_bounds__(NTHREADS, 6) void hyena_main(
    const float* __restrict__ x1g, const float* __restrict__ x2g,
    const float* __restrict__ vg,  const float* __restrict__ biasg,
    float* __restrict__ outg)
{
    extern __shared__ float2 sm[];
    float2* z_sh = sm;                                            // [NPAIR][ZSTR]
    float*  k_sh = reinterpret_cast<float*>(z_sh + NPAIR * ZSTR); // [8][KSTRF]

    const int tid   = threadIdx.x;
    const int b     = blockIdx.z;
    const int dblk  = blockIdx.y;                 // 0..31
    const int t0b   = blockIdx.x * (TPC * T_TILE);// CTA's first tile start
    const int dbase = dblk * (2 * NPAIR);         // 32 channels per block

    // ---- stage filter ONCE per CTA: 8 groups x 128 taps ----
    {
        const int gbase = dbase >> 2;             // group = d/4
        for (int i = tid; i < 8 * LCACHE; i += NTHREADS) {
            int gl = i >> 7, tau = i & 127;
            k_sh[gl * KSTRF + tau] = g_k[(gbase + gl) * LCACHE + tau];
        }
    }

    // staging identity (shared by full-stage / copy+fill)
    const int p = tid >> 3;                       // pair 0..15
    const int s = tid & 7;                        // 8 threads per pair
    const int d0s = dbase + 2 * p;
    const size_t rs0 = ((size_t)b * DMODEL + d0s) * SEQ_L;
    const size_t rs1 = rs0 + SEQ_L;
    float2* zrow_st = z_sh + p * ZSTR;

    // compute identity
    const int pair   = tid & 15;
    const int tslice = tid >> 4;                   // 0..7
    const int tb_loc = 128 + tslice * 16;
    const float*  krow = k_sh + (pair >> 1) * KSTRF;
    const float2* zrow = z_sh + pair * ZSTR;
    const float2* zbase = zrow + (tb_loc - 127);   // abs index 0 of window

    // epilogue identity (hoisted)
    const int d0e = dbase + pair * 2;
    const float2 bb = *reinterpret_cast<const float2*>(biasg + d0e);
    const unsigned long long bpk = *reinterpret_cast<const unsigned long long*>(&bb);
    const size_t x1off = ((size_t)b * DMODEL + d0e) * SEQ_L;

    for (int n = 0; n < TPC; ++n) {
        const int t0 = t0b + n * T_TILE;

        if (n == 0) {
            // ---- full stage: z = x2*v for window [t0-128, t0+128) ----
            #pragma unroll 4
            for (int c = 0; c < 8; ++c) {
                const int idx = c * 8 + s;            // float4 index 0..63
                const int tg  = t0 - 128 + 4 * idx;
                float4 a0, a1, v0, v1;
                if (tg >= 0) {
                    a0 = *reinterpret_cast<const float4*>(x2g + rs0 + tg);
                    a1 = *reinterpret_cast<const float4*>(x2g + rs1 + tg);
                    v0 = *reinterpret_cast<const float4*>(vg  + rs0 + tg);
                    v1 = *reinterpret_cast<const float4*>(vg  + rs1 + tg);
                } else {
                    a0 = a1 = v0 = v1 = make_float4(0.f, 0.f, 0.f, 0.f);
                }
                float2* zp = zrow_st + 4 * idx;
                zp[0] = make_float2(a0.x * v0.x, a1.x * v1.x);
                zp[1] = make_float2(a0.y * v0.y, a1.y * v1.y);
                zp[2] = make_float2(a0.z * v0.z, a1.z * v1.z);
                zp[3] = make_float2(a0.w * v0.w, a1.w * v1.w);
            }
        } else {
            // ---- halo reuse: copy window upper half -> lower half, fill new 128 t.
            // Per thread, copy-read set == fill-write set (slots 128+off), so no
            // intra-stage barrier needed; barrier after previous epilogue ordered
            // these writes against all compute reads.
            #pragma unroll
            for (int c = 0; c < 4; ++c) {
                const int idx = c * 8 + s;            // float4 index 0..31
                const int off = 4 * idx;              // float2 offset 0..124
                // copy old [128+off .. 128+off+3] -> [off .. off+3]
                float2 c0 = zrow_st[128 + off + 0];
                float2 c1 = zrow_st[128 + off + 1];
                float2 c2 = zrow_st[128 + off + 2];
                float2 c3 = zrow_st[128 + off + 3];
                zrow_st[off + 0] = c0;
                zrow_st[off + 1] = c1;
                zrow_st[off + 2] = c2;
                zrow_st[off + 3] = c3;
                // fill new timesteps t0+off .. t0+off+3 into [128+off ..]
                const int tg = t0 + off;
                float4 a0 = *reinterpret_cast<const float4*>(x2g + rs0 + tg);
                float4 a1 = *reinterpret_cast<const float4*>(x2g + rs1 + tg);
                float4 v0 = *reinterpret_cast<const float4*>(vg  + rs0 + tg);
                float4 v1 = *reinterpret_cast<const float4*>(vg  + rs1 + tg);
                float2* zp = zrow_st + 128 + off;
                zp[0] = make_float2(a0.x * v0.x, a1.x * v1.x);
                zp[1] = make_float2(a0.y * v0.y, a1.y * v1.y);
                zp[2] = make_float2(a0.z * v0.z, a1.z * v1.z);
                zp[3] = make_float2(a0.w * v0.w, a1.w * v1.w);
            }
        }
        __syncthreads();

        // ---- compute: each thread owns 1 channel pair x 16 timesteps ----
        unsigned long long acc[16];
        #pragma unroll
        for (int j = 0; j < 16; ++j) acc[j] = 0ull;

        // circular register window over 20 slots; abs a -> slot a%20.
        // group g: taps tau = 127-(4g+dt), reads abs [4g, 4g+18]. Refill AFTER compute.
        unsigned long long r[20];
        #pragma unroll
        for (int i = 0; i < 19; ++i) r[i] = ld2(zbase + i);

        #pragma unroll
        for (int g = 0; g < 32; ++g) {
            const float4 kq = *reinterpret_cast<const float4*>(krow + (124 - 4 * g));
            {
                const unsigned long long kk = pack2(kq.w);
                #pragma unroll
                for (int j = 0; j < 16; ++j) fma2(acc[j], kk, r[(4 * g + 0 + j) % 20]);
            }
            {
                const unsigned long long kk = pack2(kq.z);
                #pragma unroll
                for (int j = 0; j < 16; ++j) fma2(acc[j], kk, r[(4 * g + 1 + j) % 20]);
            }
            {
                const unsigned long long kk = pack2(kq.y);
                #pragma unroll
                for (int j = 0; j < 16; ++j) fma2(acc[j], kk, r[(4 * g + 2 + j) % 20]);
            }
            {
                const unsigned long long kk = pack2(kq.x);
                #pragma unroll
                for (int j = 0; j < 16; ++j) fma2(acc[j], kk, r[(4 * g + 3 + j) % 20]);
            }
            if (g < 31) {
                #pragma unroll
                for (int m = 0; m < 4; ++m) {
                    const int a = 4 * g + 19 + m;
                    r[a % 20] = ld2(zbase + a);
                }
            }
        }

        // ---- epilogue: out = (y + z*bias) * x1 ----
        // window holds abs 123..142 = z[tb_loc-4 .. tb_loc+15]; zt(j) = abs 127+j
        const float* x1r0 = x1g + x1off + t0 + tslice * 16;
        const float* x1r1 = x1r0 + SEQ_L;
        float4 xa[4], xb[4];
        #pragma unroll
        for (int q = 0; q < 4; ++q) {
            xa[q] = *reinterpret_cast<const float4*>(x1r0 + 4 * q);
            xb[q] = *reinterpret_cast<const float4*>(x1r1 + 4 * q);
        }

        float* op = outg + ((size_t)b * SEQ_L + (size_t)(t0 + tslice * 16)) * DMODEL + d0e;
        #pragma unroll
        for (int j = 0; j < 16; ++j) {
            const unsigned long long zt = r[(127 + j) % 20];
            fma2(acc[j], zt, bpk);                          // y + z*bias
            float2 res = *reinterpret_cast<float2*>(&acc[j]);
            const float* pxa = reinterpret_cast<const float*>(&xa[j >> 2]);
            const float* pxb = reinterpret_cast<const float*>(&xb[j >> 2]);
            res.x *= pxa[j & 3];
            res.y *= pxb[j & 3];
            *reinterpret_cast<float2*>(op + (size_t)j * DMODEL) = res;
        }

        __syncthreads();   // all compute reads of z_sh done before next staging
    }
}

extern "C" void kernel_launch(void* const* d_in, const int* in_sizes, int n_in,
                              void* d_out, int out_size) {
    const float* x1 = (const float*)d_in[0];
    const float* x2 = (const float*)d_in[1];
    const float* v  = (const float*)d_in[2];
    const float* h  = (const float*)d_in[3];
    const float* cb = (const float*)d_in[4];
    float* out = (float*)d_out;

    cudaFuncSetAttribute(hyena_main, cudaFuncAttributeMaxDynamicSharedMemorySize, SMEM_BYTES);

    build_filter<<<NGROUP, LCACHE>>>(h);

    dim3 grid(SEQ_L / (T_TILE * TPC), DMODEL / (2 * NPAIR), NBATCH);  // (16, 32, 2)
    hyena_main<<<grid, NTHREADS, SMEM_BYTES>>>(x1, x2, v, cb, out);
}